// round 5
// baseline (speedup 1.0000x reference)
#include <cuda_runtime.h>
#include <math.h>

#define BB 64
#define SS 1024
#define DK 128
#define DV 128
#define QTR 32
#define KPAD 36   // padded chunk stride (floats): 36*4B=144B -> h-groups on disjoint bank quads

// Normalized keys (32 MB) + adjacent-key dots c[s] = kn[s-1]·kn[s] (256 KB).
__device__ float g_kn[(size_t)BB * SS * DK];
__device__ float g_c[BB * SS];

// ---------------------------------------------------------------------------
// Pre-pass (fully parallel): normalize keys, adjacent normalized dots.
// ---------------------------------------------------------------------------
__global__ void prep_kernel(const float* __restrict__ key) {
    int row = blockIdx.x * 8 + (threadIdx.x >> 5);
    int lane = threadIdx.x & 31;
    if (row >= BB * SS) return;
    int s = row & (SS - 1);

    float4 kv = reinterpret_cast<const float4*>(key)[(size_t)row * 32 + lane];
    float nn = kv.x * kv.x + kv.y * kv.y + kv.z * kv.z + kv.w * kv.w;
    float np = 0.f, dd = 0.f;
    if (s > 0) {
        float4 kp = reinterpret_cast<const float4*>(key)[(size_t)(row - 1) * 32 + lane];
        np = kp.x * kp.x + kp.y * kp.y + kp.z * kp.z + kp.w * kp.w;
        dd = kv.x * kp.x + kv.y * kp.y + kv.z * kp.z + kv.w * kp.w;
    }
    #pragma unroll
    for (int o = 16; o; o >>= 1) {
        nn += __shfl_xor_sync(0xffffffffu, nn, o);
        np += __shfl_xor_sync(0xffffffffu, np, o);
        dd += __shfl_xor_sync(0xffffffffu, dd, o);
    }
    float invn = 1.0f / (sqrtf(nn) + 1e-6f);
    float4 o4 = make_float4(kv.x * invn, kv.y * invn, kv.z * invn, kv.w * invn);
    reinterpret_cast<float4*>(g_kn)[(size_t)row * 32 + lane] = o4;
    if (lane == 0)
        g_c[row] = (s > 0) ? dd * invn * (1.0f / (sqrtf(np) + 1e-6f)) : 0.0f;
}

// ---------------------------------------------------------------------------
// Packed f32x2 helpers
// ---------------------------------------------------------------------------
__device__ __forceinline__ unsigned long long pack2(float x) {
    unsigned long long r;
    asm("mov.b64 %0, {%1, %1};" : "=l"(r) : "f"(x));
    return r;
}
__device__ __forceinline__ void fma2(unsigned long long& d,
                                     unsigned long long a, unsigned long long b) {
    asm("fma.rn.f32x2 %0, %1, %2, %0;" : "+l"(d) : "l"(a), "l"(b));
}
__device__ __forceinline__ float sum2(unsigned long long a) {
    float lo, hi;
    asm("mov.b64 {%0, %1}, %2;" : "=f"(lo), "=f"(hi) : "l"(a));
    return lo + hi;
}

// ---------------------------------------------------------------------------
// Sequential scan: one CTA per batch, 512 threads. Thread (r=t>>2, h=t&3)
// owns a 32-float quarter of memory row r (16 f32x2 regs). Full dot via
// shfl_xor(1)+shfl_xor(2). One-step-deferred rank-1 update. 4 warps/SMSP.
// ---------------------------------------------------------------------------
__global__ __launch_bounds__(512, 1) void sgm_kernel(
    const float* __restrict__ memory,
    const float* __restrict__ value,
    float* __restrict__ out)
{
    const int b = blockIdx.x;
    const int t = threadIdx.x;
    const int r = t >> 2;
    const int h = t & 3;
    const int lane = t & 31;
    const int wid = t >> 5;

    __shared__ __align__(16) float sk[3][4 * KPAD];
    __shared__ float red[2][16];

    const float* knb = g_kn + (size_t)b * SS * DK;
    const float* vb  = value + (size_t)b * SS * DV;
    const float* cb  = g_c + (size_t)b * SS;
    float* gates = out + (size_t)BB * DV * DK + (size_t)b * SS;

    // Load my 32-float quarter of memory row r as 16 packed f32x2.
    unsigned long long m2[QTR / 2];
    {
        const ulonglong2* mb = reinterpret_cast<const ulonglong2*>(
            memory + (size_t)b * DV * DK + (size_t)r * DK + h * QTR);
        #pragma unroll
        for (int j = 0; j < QTR / 4; ++j) {
            ulonglong2 x = mb[j];
            m2[2 * j] = x.x; m2[2 * j + 1] = x.y;
        }
    }

    // ---- prologue: stage k0, compute step-0 dot/reduce ----
    if (t < DK) sk[0][(t >> 5) * KPAD + (t & 31)] = knb[t];
    float vs = vb[r];
    float ccur = cb[1];
    __syncthreads();

    float pprev, sprev;
    {
        const ulonglong2* kc = reinterpret_cast<const ulonglong2*>(&sk[0][h * KPAD]);
        unsigned long long a0 = 0, a1 = 0, a2 = 0, a3 = 0;
        #pragma unroll
        for (int j = 0; j < 2; ++j) {
            ulonglong2 k0 = kc[4 * j], k1 = kc[4 * j + 1];
            ulonglong2 k2 = kc[4 * j + 2], k3 = kc[4 * j + 3];
            fma2(a0, m2[8 * j + 0], k0.x); fma2(a1, m2[8 * j + 1], k0.y);
            fma2(a2, m2[8 * j + 2], k1.x); fma2(a3, m2[8 * j + 3], k1.y);
            fma2(a0, m2[8 * j + 4], k2.x); fma2(a1, m2[8 * j + 5], k2.y);
            fma2(a2, m2[8 * j + 6], k3.x); fma2(a3, m2[8 * j + 7], k3.y);
        }
        float part = (sum2(a0) + sum2(a1)) + (sum2(a2) + sum2(a3));
        part += __shfl_xor_sync(0xffffffffu, part, 1);
        float pred = part + __shfl_xor_sync(0xffffffffu, part, 2);
        float sur = pred - vs;
        float ss2 = 0.25f * sur * sur;           // quads duplicate -> quarter
        #pragma unroll
        for (int o = 16; o; o >>= 1) ss2 += __shfl_xor_sync(0xffffffffu, ss2, o);
        if (lane == 0) red[0][wid] = ss2;
        pprev = pred; sprev = sur;
    }
    if (t < DK) sk[1][(t >> 5) * KPAD + (t & 31)] = knb[DK + t];
    vs = vb[DV + r];
    __syncthreads();

    int ip = 2, ic = 0, inx = 1;  // rotate at loop top -> ip=kn[s-1], ic=kn[s]

    for (int s = 1; s < SS; ++s) {
        { int tmp = ip; ip = ic; ic = inx; inx = tmp; }

        const int sn = (s + 1 < SS) ? s + 1 : s;
        float knxt = (t < DK) ? knb[(size_t)sn * DK + t] : 0.0f;
        float vnxt = vb[(size_t)sn * DV + r];
        float cnxt = cb[sn];

        // A: quarter dot D = m_{s-2}[r, h-quarter] · kn[s]  (gate-independent)
        const ulonglong2* kc = reinterpret_cast<const ulonglong2*>(&sk[ic][h * KPAD]);
        unsigned long long a0 = 0, a1 = 0, a2 = 0, a3 = 0;
        #pragma unroll
        for (int j = 0; j < 2; ++j) {
            ulonglong2 k0 = kc[4 * j], k1 = kc[4 * j + 1];
            ulonglong2 k2 = kc[4 * j + 2], k3 = kc[4 * j + 3];
            fma2(a0, m2[8 * j + 0], k0.x); fma2(a1, m2[8 * j + 1], k0.y);
            fma2(a2, m2[8 * j + 2], k1.x); fma2(a3, m2[8 * j + 3], k1.y);
            fma2(a0, m2[8 * j + 4], k2.x); fma2(a1, m2[8 * j + 5], k2.y);
            fma2(a2, m2[8 * j + 6], k3.x); fma2(a3, m2[8 * j + 7], k3.y);
        }

        // B: finalize gate of step s-1
        const float* rp = red[(s - 1) & 1];
        float t0 = ((rp[0] + rp[1]) + (rp[2] + rp[3]))
                 + ((rp[4] + rp[5]) + (rp[6] + rp[7]));
        float t1 = ((rp[8] + rp[9]) + (rp[10] + rp[11]))
                 + ((rp[12] + rp[13]) + (rp[14] + rp[15]));
        float snorm = sqrtf(t0 + t1);
        float gate = 1.0f / (1.0f + __expf((0.1f - snorm) * 10.0f));
        if (t == 0) gates[s - 1] = gate;
        float u = gate * fmaf(0.1f, sprev, pprev);

        // C: deferred rank-1 update m -= u * kn[s-1]
        unsigned long long nu = pack2(-u);
        const ulonglong2* kp = reinterpret_cast<const ulonglong2*>(&sk[ip][h * KPAD]);
        #pragma unroll
        for (int j = 0; j < 2; ++j) {
            ulonglong2 k0 = kp[4 * j], k1 = kp[4 * j + 1];
            ulonglong2 k2 = kp[4 * j + 2], k3 = kp[4 * j + 3];
            fma2(m2[8 * j + 0], k0.x, nu); fma2(m2[8 * j + 1], k0.y, nu);
            fma2(m2[8 * j + 2], k1.x, nu); fma2(m2[8 * j + 3], k1.y, nu);
            fma2(m2[8 * j + 4], k2.x, nu); fma2(m2[8 * j + 5], k2.y, nu);
            fma2(m2[8 * j + 6], k3.x, nu); fma2(m2[8 * j + 7], k3.y, nu);
        }

        // D: assemble pred_s (with deferred correction), surprise, reduce
        float part = (sum2(a0) + sum2(a1)) + (sum2(a2) + sum2(a3));
        part += __shfl_xor_sync(0xffffffffu, part, 1);
        float pred = (part + __shfl_xor_sync(0xffffffffu, part, 2)) - u * ccur;
        float sur = pred - vs;
        float ss2 = 0.25f * sur * sur;
        #pragma unroll
        for (int o = 16; o; o >>= 1) ss2 += __shfl_xor_sync(0xffffffffu, ss2, o);
        if (lane == 0) red[s & 1][wid] = ss2;

        pprev = pred; sprev = sur; vs = vnxt; ccur = cnxt;
        if (t < DK) sk[inx][(t >> 5) * KPAD + (t & 31)] = knxt;
        __syncthreads();
    }

    // ---- epilogue: gate + update for step SS-1 (kn[SS-1] is in sk[ic]) ----
    {
        const float* rp = red[(SS - 1) & 1];
        float t0 = ((rp[0] + rp[1]) + (rp[2] + rp[3]))
                 + ((rp[4] + rp[5]) + (rp[6] + rp[7]));
        float t1 = ((rp[8] + rp[9]) + (rp[10] + rp[11]))
                 + ((rp[12] + rp[13]) + (rp[14] + rp[15]));
        float snorm = sqrtf(t0 + t1);
        float gate = 1.0f / (1.0f + __expf((0.1f - snorm) * 10.0f));
        if (t == 0) gates[SS - 1] = gate;
        float u = gate * fmaf(0.1f, sprev, pprev);
        unsigned long long nu = pack2(-u);
        const ulonglong2* kp = reinterpret_cast<const ulonglong2*>(&sk[ic][h * KPAD]);
        #pragma unroll
        for (int j = 0; j < 2; ++j) {
            ulonglong2 k0 = kp[4 * j], k1 = kp[4 * j + 1];
            ulonglong2 k2 = kp[4 * j + 2], k3 = kp[4 * j + 3];
            fma2(m2[8 * j + 0], k0.x, nu); fma2(m2[8 * j + 1], k0.y, nu);
            fma2(m2[8 * j + 2], k1.x, nu); fma2(m2[8 * j + 3], k1.y, nu);
            fma2(m2[8 * j + 4], k2.x, nu); fma2(m2[8 * j + 5], k2.y, nu);
            fma2(m2[8 * j + 6], k3.x, nu); fma2(m2[8 * j + 7], k3.y, nu);
        }
    }

    // Store final memory quarter.
    {
        ulonglong2* ob = reinterpret_cast<ulonglong2*>(
            out + (size_t)b * DV * DK + (size_t)r * DK + h * QTR);
        #pragma unroll
        for (int j = 0; j < QTR / 4; ++j) {
            ulonglong2 x;
            x.x = m2[2 * j]; x.y = m2[2 * j + 1];
            ob[j] = x;
        }
    }
}

extern "C" void kernel_launch(void* const* d_in, const int* in_sizes, int n_in,
                              void* d_out, int out_size) {
    const float* memory = (const float*)d_in[0];
    const float* key    = (const float*)d_in[1];
    const float* value  = (const float*)d_in[2];
    float* out = (float*)d_out;

    prep_kernel<<<(BB * SS) / 8, 256>>>(key);
    sgm_kernel<<<BB, 512>>>(memory, value, out);
}

// round 9
// speedup vs baseline: 1.2581x; 1.2581x over previous
#include <cuda_runtime.h>
#include <math.h>

#define BB 64
#define SS 1024
#define DK 128
#define DV 128
#define HALF 64
#define KST 68   // padded half-stride (floats); halves at +0 / +68 -> disjoint bank quads

// Normalized keys (32 MB) + adjacent-key dots c[s] = kn[s-1]·kn[s] (256 KB).
__device__ float g_kn[(size_t)BB * SS * DK];
__device__ float g_c[BB * SS];

// ---------------------------------------------------------------------------
// Pre-pass (fully parallel): normalize keys, adjacent normalized dots.
// ---------------------------------------------------------------------------
__global__ void prep_kernel(const float* __restrict__ key) {
    int row = blockIdx.x * 8 + (threadIdx.x >> 5);
    int lane = threadIdx.x & 31;
    if (row >= BB * SS) return;
    int s = row & (SS - 1);

    float4 kv = reinterpret_cast<const float4*>(key)[(size_t)row * 32 + lane];
    float nn = kv.x * kv.x + kv.y * kv.y + kv.z * kv.z + kv.w * kv.w;
    float np = 0.f, dd = 0.f;
    if (s > 0) {
        float4 kp = reinterpret_cast<const float4*>(key)[(size_t)(row - 1) * 32 + lane];
        np = kp.x * kp.x + kp.y * kp.y + kp.z * kp.z + kp.w * kp.w;
        dd = kv.x * kp.x + kv.y * kp.y + kv.z * kp.z + kv.w * kp.w;
    }
    #pragma unroll
    for (int o = 16; o; o >>= 1) {
        nn += __shfl_xor_sync(0xffffffffu, nn, o);
        np += __shfl_xor_sync(0xffffffffu, np, o);
        dd += __shfl_xor_sync(0xffffffffu, dd, o);
    }
    float invn = 1.0f / (sqrtf(nn) + 1e-6f);
    float4 o4 = make_float4(kv.x * invn, kv.y * invn, kv.z * invn, kv.w * invn);
    reinterpret_cast<float4*>(g_kn)[(size_t)row * 32 + lane] = o4;
    if (lane == 0)
        g_c[row] = (s > 0) ? dd * invn * (1.0f / (sqrtf(np) + 1e-6f)) : 0.0f;
}

// ---------------------------------------------------------------------------
// Packed f32x2 helpers
// ---------------------------------------------------------------------------
__device__ __forceinline__ unsigned long long pack2(float x) {
    unsigned long long r;
    asm("mov.b64 %0, {%1, %1};" : "=l"(r) : "f"(x));
    return r;
}
__device__ __forceinline__ void fma2(unsigned long long& d,
                                     unsigned long long a, unsigned long long b) {
    asm("fma.rn.f32x2 %0, %1, %2, %0;" : "+l"(d) : "l"(a), "l"(b));
}
__device__ __forceinline__ float sum2(unsigned long long a) {
    float lo, hi;
    asm("mov.b64 {%0, %1}, %2;" : "=f"(lo), "=f"(hi) : "l"(a));
    return lo + hi;
}

// ---------------------------------------------------------------------------
// Sequential scan: one CTA per batch, 256 threads. Thread (r=t>>1, h=t&1)
// owns 64 floats of memory row r (32 f32x2 regs). Full dot recovered with
// one shfl_xor(1). One-step-deferred rank-1 update. 2 warps/SMSP.
// ---------------------------------------------------------------------------
__global__ __launch_bounds__(256, 1) void sgm_kernel(
    const float* __restrict__ memory,
    const float* __restrict__ value,
    float* __restrict__ out)
{
    const int b = blockIdx.x;
    const int t = threadIdx.x;
    const int r = t >> 1;
    const int h = t & 1;
    const int lane = t & 31;
    const int wid = t >> 5;

    __shared__ __align__(16) float sk[3][2 * KST];
    __shared__ __align__(32) float red[2][8];

    const float* knb = g_kn + (size_t)b * SS * DK;
    const float* vb  = value + (size_t)b * SS * DV;
    const float* cb  = g_c + (size_t)b * SS;
    float* gates = out + (size_t)BB * DV * DK + (size_t)b * SS;

    // Load my 64-float half of memory row r as 32 packed f32x2.
    unsigned long long m2[HALF / 2];
    {
        const ulonglong2* mb = reinterpret_cast<const ulonglong2*>(
            memory + (size_t)b * DV * DK + (size_t)r * DK + h * HALF);
        #pragma unroll
        for (int j = 0; j < HALF / 4; ++j) {
            ulonglong2 x = mb[j];
            m2[2 * j] = x.x; m2[2 * j + 1] = x.y;
        }
    }

    // ---- prologue: stage k0, compute step-0 dot/reduce ----
    if (t < DK) sk[0][(t >> 6) * KST + (t & 63)] = knb[t];
    float vs = vb[r];
    float ccur = cb[1];
    __syncthreads();

    float pprev, sprev;
    {
        const ulonglong2* kc = reinterpret_cast<const ulonglong2*>(&sk[0][h * KST]);
        unsigned long long a0 = 0, a1 = 0, a2 = 0, a3 = 0;
        #pragma unroll
        for (int j = 0; j < 4; ++j) {
            ulonglong2 k0 = kc[4 * j], k1 = kc[4 * j + 1];
            ulonglong2 k2 = kc[4 * j + 2], k3 = kc[4 * j + 3];
            fma2(a0, m2[8 * j + 0], k0.x); fma2(a1, m2[8 * j + 1], k0.y);
            fma2(a2, m2[8 * j + 2], k1.x); fma2(a3, m2[8 * j + 3], k1.y);
            fma2(a0, m2[8 * j + 4], k2.x); fma2(a1, m2[8 * j + 5], k2.y);
            fma2(a2, m2[8 * j + 6], k3.x); fma2(a3, m2[8 * j + 7], k3.y);
        }
        float part = (sum2(a0) + sum2(a1)) + (sum2(a2) + sum2(a3));
        float pred = part + __shfl_xor_sync(0xffffffffu, part, 1);
        float sur = pred - vs;
        // pairs duplicate sur; same-parity orbit (xor 2,4,8,16) sums each of
        // the warp's 16 rows exactly once -> no 0.5 factor.
        float ss2 = sur * sur;
        ss2 += __shfl_xor_sync(0xffffffffu, ss2, 2);
        ss2 += __shfl_xor_sync(0xffffffffu, ss2, 4);
        ss2 += __shfl_xor_sync(0xffffffffu, ss2, 8);
        ss2 += __shfl_xor_sync(0xffffffffu, ss2, 16);
        if (lane == 0) red[0][wid] = ss2;
        pprev = pred; sprev = sur;
    }
    if (t < DK) sk[1][(t >> 6) * KST + (t & 63)] = knb[DK + t];
    vs = vb[DV + r];
    __syncthreads();

    int ip = 2, ic = 0, inx = 1;  // rotate at loop top -> ip=0(kn[s-1]), ic=1(kn[s])

    for (int s = 1; s < SS; ++s) {
        { int tmp = ip; ip = ic; ic = inx; inx = tmp; }

        const int sn = (s + 1 < SS) ? s + 1 : s;
        float knxt = (t < DK) ? knb[(size_t)sn * DK + t] : 0.0f;
        float vnxt = vb[(size_t)sn * DV + r];
        float cnxt = cb[sn];

        // A: partial dot D = m_{s-1}[r, h-half] · kn[s]  (gate-independent)
        const ulonglong2* kc = reinterpret_cast<const ulonglong2*>(&sk[ic][h * KST]);
        unsigned long long a0 = 0, a1 = 0, a2 = 0, a3 = 0;
        #pragma unroll
        for (int j = 0; j < 4; ++j) {
            ulonglong2 k0 = kc[4 * j], k1 = kc[4 * j + 1];
            ulonglong2 k2 = kc[4 * j + 2], k3 = kc[4 * j + 3];
            fma2(a0, m2[8 * j + 0], k0.x); fma2(a1, m2[8 * j + 1], k0.y);
            fma2(a2, m2[8 * j + 2], k1.x); fma2(a3, m2[8 * j + 3], k1.y);
            fma2(a0, m2[8 * j + 4], k2.x); fma2(a1, m2[8 * j + 5], k2.y);
            fma2(a2, m2[8 * j + 6], k3.x); fma2(a3, m2[8 * j + 7], k3.y);
        }

        // B: finalize gate of step s-1 (red written before last barrier)
        const float* rp = red[(s - 1) & 1];
        float4 rA = *reinterpret_cast<const float4*>(&rp[0]);
        float4 rB = *reinterpret_cast<const float4*>(&rp[4]);
        float tot = ((rA.x + rA.y) + (rA.z + rA.w))
                  + ((rB.x + rB.y) + (rB.z + rB.w));
        float snorm = sqrtf(tot);
        float gate = 1.0f / (1.0f + __expf((0.1f - snorm) * 10.0f));
        if (t == 0) gates[s - 1] = gate;
        float u = gate * fmaf(0.1f, sprev, pprev);

        // D: assemble pred_s (deferred correction), surprise, reduce, STS
        float part = (sum2(a0) + sum2(a1)) + (sum2(a2) + sum2(a3));
        float pred = (part + __shfl_xor_sync(0xffffffffu, part, 1)) - u * ccur;
        float sur = pred - vs;
        float ss2 = sur * sur;
        ss2 += __shfl_xor_sync(0xffffffffu, ss2, 2);
        ss2 += __shfl_xor_sync(0xffffffffu, ss2, 4);
        ss2 += __shfl_xor_sync(0xffffffffu, ss2, 8);
        ss2 += __shfl_xor_sync(0xffffffffu, ss2, 16);
        if (lane == 0) red[s & 1][wid] = ss2;

        // C: deferred rank-1 update m -= u * kn[s-1]  (after the reduce so its
        // FFMA2 issue hides in the shfl-latency shadow; independent of D)
        unsigned long long nu = pack2(-u);
        const ulonglong2* kp = reinterpret_cast<const ulonglong2*>(&sk[ip][h * KST]);
        #pragma unroll
        for (int j = 0; j < 4; ++j) {
            ulonglong2 k0 = kp[4 * j], k1 = kp[4 * j + 1];
            ulonglong2 k2 = kp[4 * j + 2], k3 = kp[4 * j + 3];
            fma2(m2[8 * j + 0], k0.x, nu); fma2(m2[8 * j + 1], k0.y, nu);
            fma2(m2[8 * j + 2], k1.x, nu); fma2(m2[8 * j + 3], k1.y, nu);
            fma2(m2[8 * j + 4], k2.x, nu); fma2(m2[8 * j + 5], k2.y, nu);
            fma2(m2[8 * j + 6], k3.x, nu); fma2(m2[8 * j + 7], k3.y, nu);
        }

        pprev = pred; sprev = sur; vs = vnxt; ccur = cnxt;
        if (t < DK) sk[inx][(t >> 6) * KST + (t & 63)] = knxt;
        __syncthreads();
    }

    // ---- epilogue: gate + update for step SS-1 (kn[SS-1] is in sk[ic]) ----
    {
        const float* rp = red[(SS - 1) & 1];
        float4 rA = *reinterpret_cast<const float4*>(&rp[0]);
        float4 rB = *reinterpret_cast<const float4*>(&rp[4]);
        float tot = ((rA.x + rA.y) + (rA.z + rA.w))
                  + ((rB.x + rB.y) + (rB.z + rB.w));
        float snorm = sqrtf(tot);
        float gate = 1.0f / (1.0f + __expf((0.1f - snorm) * 10.0f));
        if (t == 0) gates[SS - 1] = gate;
        float u = gate * fmaf(0.1f, sprev, pprev);
        unsigned long long nu = pack2(-u);
        const ulonglong2* kp = reinterpret_cast<const ulonglong2*>(&sk[ic][h * KST]);
        #pragma unroll
        for (int j = 0; j < 4; ++j) {
            ulonglong2 k0 = kp[4 * j], k1 = kp[4 * j + 1];
            ulonglong2 k2 = kp[4 * j + 2], k3 = kp[4 * j + 3];
            fma2(m2[8 * j + 0], k0.x, nu); fma2(m2[8 * j + 1], k0.y, nu);
            fma2(m2[8 * j + 2], k1.x, nu); fma2(m2[8 * j + 3], k1.y, nu);
            fma2(m2[8 * j + 4], k2.x, nu); fma2(m2[8 * j + 5], k2.y, nu);
            fma2(m2[8 * j + 6], k3.x, nu); fma2(m2[8 * j + 7], k3.y, nu);
        }
    }

    // Store final memory half.
    {
        ulonglong2* ob = reinterpret_cast<ulonglong2*>(
            out + (size_t)b * DV * DK + (size_t)r * DK + h * HALF);
        #pragma unroll
        for (int j = 0; j < HALF / 4; ++j) {
            ulonglong2 x;
            x.x = m2[2 * j]; x.y = m2[2 * j + 1];
            ob[j] = x;
        }
    }
}

extern "C" void kernel_launch(void* const* d_in, const int* in_sizes, int n_in,
                              void* d_out, int out_size) {
    const float* memory = (const float*)d_in[0];
    const float* key    = (const float*)d_in[1];
    const float* value  = (const float*)d_in[2];
    float* out = (float*)d_out;

    prep_kernel<<<(BB * SS) / 8, 256>>>(key);
    sgm_kernel<<<BB, 256>>>(memory, value, out);
}

// round 10
// speedup vs baseline: 1.3282x; 1.0557x over previous
#include <cuda_runtime.h>
#include <math.h>

#define BB 64
#define SS 1024
#define DK 128
#define DV 128
#define HALF 64
#define KST 68   // padded half-stride (floats); halves at +0 / +68 -> disjoint bank quads

// Normalized keys (32 MB) + gap-1 / gap-2 normalized key dots.
__device__ float g_kn[(size_t)BB * SS * DK];
__device__ float g_c1[BB * SS];
__device__ float g_c2[BB * SS];

// ---------------------------------------------------------------------------
// Pre-pass 1: normalize keys.
// ---------------------------------------------------------------------------
__global__ void knorm_kernel(const float* __restrict__ key) {
    int row = blockIdx.x * 8 + (threadIdx.x >> 5);
    int lane = threadIdx.x & 31;
    float4 kv = reinterpret_cast<const float4*>(key)[(size_t)row * 32 + lane];
    float nn = kv.x * kv.x + kv.y * kv.y + kv.z * kv.z + kv.w * kv.w;
    #pragma unroll
    for (int o = 16; o; o >>= 1) nn += __shfl_xor_sync(0xffffffffu, nn, o);
    float invn = 1.0f / (sqrtf(nn) + 1e-6f);
    float4 o4 = make_float4(kv.x * invn, kv.y * invn, kv.z * invn, kv.w * invn);
    reinterpret_cast<float4*>(g_kn)[(size_t)row * 32 + lane] = o4;
}

// ---------------------------------------------------------------------------
// Pre-pass 2: c1[s] = kn_{s-1}.kn_s, c2[s] = kn_{s-2}.kn_s (0 when out of range)
// ---------------------------------------------------------------------------
__global__ void cdots_kernel() {
    int row = blockIdx.x * 8 + (threadIdx.x >> 5);
    int lane = threadIdx.x & 31;
    int s = row & (SS - 1);
    float4 kv = reinterpret_cast<const float4*>(g_kn)[(size_t)row * 32 + lane];
    float d1 = 0.f, d2 = 0.f;
    if (s > 0) {
        float4 kp = reinterpret_cast<const float4*>(g_kn)[(size_t)(row - 1) * 32 + lane];
        d1 = kv.x * kp.x + kv.y * kp.y + kv.z * kp.z + kv.w * kp.w;
    }
    if (s > 1) {
        float4 kq = reinterpret_cast<const float4*>(g_kn)[(size_t)(row - 2) * 32 + lane];
        d2 = kv.x * kq.x + kv.y * kq.y + kv.z * kq.z + kv.w * kq.w;
    }
    #pragma unroll
    for (int o = 16; o; o >>= 1) {
        d1 += __shfl_xor_sync(0xffffffffu, d1, o);
        d2 += __shfl_xor_sync(0xffffffffu, d2, o);
    }
    if (lane == 0) { g_c1[row] = d1; g_c2[row] = d2; }
}

// ---------------------------------------------------------------------------
// Packed f32x2 helpers
// ---------------------------------------------------------------------------
__device__ __forceinline__ unsigned long long pack2(float x) {
    unsigned long long r;
    asm("mov.b64 %0, {%1, %1};" : "=l"(r) : "f"(x));
    return r;
}
__device__ __forceinline__ void fma2(unsigned long long& d,
                                     unsigned long long a, unsigned long long b) {
    asm("fma.rn.f32x2 %0, %1, %2, %0;" : "+l"(d) : "l"(a), "l"(b));
}
__device__ __forceinline__ float sum2(unsigned long long a) {
    float lo, hi;
    asm("mov.b64 {%0, %1}, %2;" : "=f"(lo), "=f"(hi) : "l"(a));
    return lo + hi;
}

// ---------------------------------------------------------------------------
// Main scan: one CTA/batch, 256 threads, pair layout (r=t>>1, h=t&1), 64-float
// half-row of m in 32 f32x2 regs. Lazy memory (updates applied 2 steps late,
// 4-slot kn ring), gate chain decoupled via the quadratic-form identity:
//   ||sur_s||^2 = A_s - 2*m1*B_s + m1^2*C_s,  m1 = c1[s]*g_{s-1}.
// ---------------------------------------------------------------------------
__global__ __launch_bounds__(256, 1) void sgm_kernel(
    const float* __restrict__ memory,
    const float* __restrict__ value,
    float* __restrict__ out)
{
    const int b = blockIdx.x;
    const int t = threadIdx.x;
    const int r = t >> 1;
    const int h = t & 1;
    const int lane = t & 31;
    const int wid = t >> 5;

    __shared__ __align__(16) float sk[4][2 * KST];
    __shared__ __align__(16) float red[2][3][8];   // [buf][A/B/C][warp]

    const float* knb = g_kn + (size_t)b * SS * DK;
    const float* vb  = value + (size_t)b * SS * DV;
    const float* c1b = g_c1 + (size_t)b * SS;
    const float* c2b = g_c2 + (size_t)b * SS;
    float* gates = out + (size_t)BB * DV * DK + (size_t)b * SS;

    // Load my 64-float half of memory row r as 32 packed f32x2.
    unsigned long long m2[HALF / 2];
    {
        const ulonglong2* mb = reinterpret_cast<const ulonglong2*>(
            memory + (size_t)b * DV * DK + (size_t)r * DK + h * HALF);
        #pragma unroll
        for (int j = 0; j < HALF / 4; ++j) {
            ulonglong2 x = mb[j];
            m2[2 * j] = x.x; m2[2 * j + 1] = x.y;
        }
    }

    // ---- prologue: stage kn_0, zero slot 3 (read as zero-update at s=1) ----
    if (t < DK) sk[0][(t >> 6) * KST + (t & 63)] = knb[t];
    if (t < 2 * KST) sk[3][t] = 0.0f;
    float vs = vb[r];                 // v_0
    __syncthreads();

    // step 0: D_0, sur0_0, reduces (B=C=0 since w_{-1}=0)
    float sur0p, vprev;
    {
        const ulonglong2* kc = reinterpret_cast<const ulonglong2*>(&sk[0][h * KST]);
        unsigned long long a0 = 0, a1 = 0, a2 = 0, a3 = 0;
        #pragma unroll
        for (int j = 0; j < 4; ++j) {
            ulonglong2 k0 = kc[4 * j], k1 = kc[4 * j + 1];
            ulonglong2 k2 = kc[4 * j + 2], k3 = kc[4 * j + 3];
            fma2(a0, m2[8 * j + 0], k0.x); fma2(a1, m2[8 * j + 1], k0.y);
            fma2(a2, m2[8 * j + 2], k1.x); fma2(a3, m2[8 * j + 3], k1.y);
            fma2(a0, m2[8 * j + 4], k2.x); fma2(a1, m2[8 * j + 5], k2.y);
            fma2(a2, m2[8 * j + 6], k3.x); fma2(a3, m2[8 * j + 7], k3.y);
        }
        float part = (sum2(a0) + sum2(a1)) + (sum2(a2) + sum2(a3));
        float pred = part + __shfl_xor_sync(0xffffffffu, part, 1);
        float sur0 = pred - vs;
        float aa = sur0 * sur0;   // pair lanes duplicate; same-parity orbit sums 16 rows
        aa += __shfl_xor_sync(0xffffffffu, aa, 2);
        aa += __shfl_xor_sync(0xffffffffu, aa, 4);
        aa += __shfl_xor_sync(0xffffffffu, aa, 8);
        aa += __shfl_xor_sync(0xffffffffu, aa, 16);
        if (lane == 0) {
            red[0][0][wid] = aa; red[0][1][wid] = 0.0f; red[0][2][wid] = 0.0f;
        }
        sur0p = sur0; vprev = vs;
    }
    // stage kn_1, load step-1 inputs
    if (t < DK) sk[1][(t >> 6) * KST + (t & 63)] = knb[DK + t];
    vs = vb[DV + r];
    float c1cur = c1b[1], c2cur = c2b[1];
    float g1 = 0.0f, w2 = 0.0f, c1p = 0.0f;   // g_{-1}, w_{-1}, c1[0]
    __syncthreads();

    for (int s = 1; s < SS; ++s) {
        const int sn = (s + 1 < SS) ? s + 1 : s;
        float knxt = (t < DK) ? knb[(size_t)sn * DK + t] : 0.0f;
        float vnxt = vb[(size_t)sn * DV + r];
        float c1nxt = c1b[sn], c2nxt = c2b[sn];

        // A: D_s = m(<=s-3) . kn_s   (slot s&3)
        const ulonglong2* kc = reinterpret_cast<const ulonglong2*>(&sk[s & 3][h * KST]);
        unsigned long long a0 = 0, a1 = 0, a2 = 0, a3 = 0;
        #pragma unroll
        for (int j = 0; j < 4; ++j) {
            ulonglong2 k0 = kc[4 * j], k1 = kc[4 * j + 1];
            ulonglong2 k2 = kc[4 * j + 2], k3 = kc[4 * j + 3];
            fma2(a0, m2[8 * j + 0], k0.x); fma2(a1, m2[8 * j + 1], k0.y);
            fma2(a2, m2[8 * j + 2], k1.x); fma2(a3, m2[8 * j + 3], k1.y);
            fma2(a0, m2[8 * j + 4], k2.x); fma2(a1, m2[8 * j + 5], k2.y);
            fma2(a2, m2[8 * j + 6], k3.x); fma2(a3, m2[8 * j + 7], k3.y);
        }

        // B: scalar gate finalize for step s-1
        const float* rp = &red[(s - 1) & 1][0][0];
        float4 pA0 = *reinterpret_cast<const float4*>(&rp[0]);
        float4 pA1 = *reinterpret_cast<const float4*>(&rp[4]);
        float4 pB0 = *reinterpret_cast<const float4*>(&rp[8]);
        float4 pB1 = *reinterpret_cast<const float4*>(&rp[12]);
        float4 pC0 = *reinterpret_cast<const float4*>(&rp[16]);
        float4 pC1 = *reinterpret_cast<const float4*>(&rp[20]);
        float Av = ((pA0.x + pA0.y) + (pA0.z + pA0.w))
                 + ((pA1.x + pA1.y) + (pA1.z + pA1.w));
        float Bv = ((pB0.x + pB0.y) + (pB0.z + pB0.w))
                 + ((pB1.x + pB1.y) + (pB1.z + pB1.w));
        float Cv = ((pC0.x + pC0.y) + (pC0.z + pC0.w))
                 + ((pC1.x + pC1.y) + (pC1.z + pC1.w));
        float m1 = c1p * g1;
        float S2 = fmaf(m1 * m1, Cv, fmaf(-2.0f * m1, Bv, Av));
        float snorm = sqrtf(fmaxf(S2, 0.0f));
        float g0 = 1.0f / (1.0f + __expf((0.1f - snorm) * 10.0f));  // g_{s-1}
        if (t == 0) gates[s - 1] = g0;

        // C: per-row scalars
        float surprev = fmaf(-m1, w2, sur0p);        // sur_{s-1}
        float wprev   = fmaf(1.1f, surprev, vprev);  // w_{s-1}
        float u2 = g1 * w2;                          // u_{s-2}
        float part = (sum2(a0) + sum2(a1)) + (sum2(a2) + sum2(a3));
        float D = part + __shfl_xor_sync(0xffffffffu, part, 1);
        float pred0 = fmaf(-c2cur, u2, D);           // D_s - c2[s]*u_{s-2}
        float sur0n = pred0 - vs;                    // sur0_s

        // D: three reductions (A_s, B_s, C_s), 1 step of slack before use
        float aa = sur0n * sur0n;
        float bb = sur0n * wprev;
        float cc = wprev * wprev;
        aa += __shfl_xor_sync(0xffffffffu, aa, 2);
        bb += __shfl_xor_sync(0xffffffffu, bb, 2);
        cc += __shfl_xor_sync(0xffffffffu, cc, 2);
        aa += __shfl_xor_sync(0xffffffffu, aa, 4);
        bb += __shfl_xor_sync(0xffffffffu, bb, 4);
        cc += __shfl_xor_sync(0xffffffffu, cc, 4);
        aa += __shfl_xor_sync(0xffffffffu, aa, 8);
        bb += __shfl_xor_sync(0xffffffffu, bb, 8);
        cc += __shfl_xor_sync(0xffffffffu, cc, 8);
        aa += __shfl_xor_sync(0xffffffffu, aa, 16);
        bb += __shfl_xor_sync(0xffffffffu, bb, 16);
        cc += __shfl_xor_sync(0xffffffffu, cc, 16);
        if (lane == 0) {
            red[s & 1][0][wid] = aa;
            red[s & 1][1][wid] = bb;
            red[s & 1][2][wid] = cc;
        }

        // E: lazy rank-1 update m -= u_{s-2} * kn_{s-2}  (slot (s-2)&3)
        unsigned long long nu = pack2(-u2);
        const ulonglong2* kp = reinterpret_cast<const ulonglong2*>(&sk[(s - 2) & 3][h * KST]);
        #pragma unroll
        for (int j = 0; j < 4; ++j) {
            ulonglong2 k0 = kp[4 * j], k1 = kp[4 * j + 1];
            ulonglong2 k2 = kp[4 * j + 2], k3 = kp[4 * j + 3];
            fma2(m2[8 * j + 0], k0.x, nu); fma2(m2[8 * j + 1], k0.y, nu);
            fma2(m2[8 * j + 2], k1.x, nu); fma2(m2[8 * j + 3], k1.y, nu);
            fma2(m2[8 * j + 4], k2.x, nu); fma2(m2[8 * j + 5], k2.y, nu);
            fma2(m2[8 * j + 6], k3.x, nu); fma2(m2[8 * j + 7], k3.y, nu);
        }

        // F: rotate state, stage kn_{s+1}
        g1 = g0; w2 = wprev; sur0p = sur0n; vprev = vs; c1p = c1cur;
        vs = vnxt; c1cur = c1nxt; c2cur = c2nxt;
        if (t < DK) sk[(s + 1) & 3][(t >> 6) * KST + (t & 63)] = knxt;
        __syncthreads();
    }

    // ---- epilogue: finalize gate SS-1, apply the two pending updates ----
    {
        const float* rp = &red[(SS - 1) & 1][0][0];
        float4 pA0 = *reinterpret_cast<const float4*>(&rp[0]);
        float4 pA1 = *reinterpret_cast<const float4*>(&rp[4]);
        float4 pB0 = *reinterpret_cast<const float4*>(&rp[8]);
        float4 pB1 = *reinterpret_cast<const float4*>(&rp[12]);
        float4 pC0 = *reinterpret_cast<const float4*>(&rp[16]);
        float4 pC1 = *reinterpret_cast<const float4*>(&rp[20]);
        float Av = ((pA0.x + pA0.y) + (pA0.z + pA0.w))
                 + ((pA1.x + pA1.y) + (pA1.z + pA1.w));
        float Bv = ((pB0.x + pB0.y) + (pB0.z + pB0.w))
                 + ((pB1.x + pB1.y) + (pB1.z + pB1.w));
        float Cv = ((pC0.x + pC0.y) + (pC0.z + pC0.w))
                 + ((pC1.x + pC1.y) + (pC1.z + pC1.w));
        float m1 = c1p * g1;
        float S2 = fmaf(m1 * m1, Cv, fmaf(-2.0f * m1, Bv, Av));
        float snorm = sqrtf(fmaxf(S2, 0.0f));
        float g0 = 1.0f / (1.0f + __expf((0.1f - snorm) * 10.0f));  // g_{SS-1}
        if (t == 0) gates[SS - 1] = g0;
        float surprev = fmaf(-m1, w2, sur0p);
        float wprev   = fmaf(1.1f, surprev, vprev);

        // u_{SS-2} on slot (SS-2)&3
        unsigned long long nu = pack2(-(g1 * w2));
        const ulonglong2* kp = reinterpret_cast<const ulonglong2*>(&sk[(SS - 2) & 3][h * KST]);
        #pragma unroll
        for (int j = 0; j < 4; ++j) {
            ulonglong2 k0 = kp[4 * j], k1 = kp[4 * j + 1];
            ulonglong2 k2 = kp[4 * j + 2], k3 = kp[4 * j + 3];
            fma2(m2[8 * j + 0], k0.x, nu); fma2(m2[8 * j + 1], k0.y, nu);
            fma2(m2[8 * j + 2], k1.x, nu); fma2(m2[8 * j + 3], k1.y, nu);
            fma2(m2[8 * j + 4], k2.x, nu); fma2(m2[8 * j + 5], k2.y, nu);
            fma2(m2[8 * j + 6], k3.x, nu); fma2(m2[8 * j + 7], k3.y, nu);
        }
        // u_{SS-1} on slot (SS-1)&3
        nu = pack2(-(g0 * wprev));
        const ulonglong2* kq = reinterpret_cast<const ulonglong2*>(&sk[(SS - 1) & 3][h * KST]);
        #pragma unroll
        for (int j = 0; j < 4; ++j) {
            ulonglong2 k0 = kq[4 * j], k1 = kq[4 * j + 1];
            ulonglong2 k2 = kq[4 * j + 2], k3 = kq[4 * j + 3];
            fma2(m2[8 * j + 0], k0.x, nu); fma2(m2[8 * j + 1], k0.y, nu);
            fma2(m2[8 * j + 2], k1.x, nu); fma2(m2[8 * j + 3], k1.y, nu);
            fma2(m2[8 * j + 4], k2.x, nu); fma2(m2[8 * j + 5], k2.y, nu);
            fma2(m2[8 * j + 6], k3.x, nu); fma2(m2[8 * j + 7], k3.y, nu);
        }
    }

    // Store final memory half.
    {
        ulonglong2* ob = reinterpret_cast<ulonglong2*>(
            out + (size_t)b * DV * DK + (size_t)r * DK + h * HALF);
        #pragma unroll
        for (int j = 0; j < HALF / 4; ++j) {
            ulonglong2 x;
            x.x = m2[2 * j]; x.y = m2[2 * j + 1];
            ob[j] = x;
        }
    }
}

extern "C" void kernel_launch(void* const* d_in, const int* in_sizes, int n_in,
                              void* d_out, int out_size) {
    const float* memory = (const float*)d_in[0];
    const float* key    = (const float*)d_in[1];
    const float* value  = (const float*)d_in[2];
    float* out = (float*)d_out;

    knorm_kernel<<<(BB * SS) / 8, 256>>>(key);
    cdots_kernel<<<(BB * SS) / 8, 256>>>();
    sgm_kernel<<<BB, 256>>>(memory, value, out);
}